// round 5
// baseline (speedup 1.0000x reference)
#include <cuda_runtime.h>

namespace {
constexpr int N_NODES  = 100000;
constexpr int HID      = 64;
constexpr int N_LAYERS = 4;
constexpr int N_EDGES  = 800000;
constexpr float EPS    = 1e-5f;
constexpr int CAP      = 64;     // bucket capacity per node (P(deg>64) ~ 0 for Poisson(8))
constexpr int WPAD     = 68;     // padded row stride (floats): 16B-aligned, 4-bank shift/row
}

// Scratch (no cudaMalloc allowed)
__device__ float g_m  [(size_t)N_NODES * HID];
__device__ float g_h  [(size_t)N_NODES * HID];
__device__ int   g_deg[N_NODES];
__device__ int   g_bkt[(size_t)N_NODES * CAP];

// ---- packed f32x2 helpers (double = 64-bit carrier of two f32) ----
__device__ __forceinline__ double ffma2(double a, double b, double c) {
    double d; asm("fma.rn.f32x2 %0,%1,%2,%3;" : "=d"(d) : "d"(a), "d"(b), "d"(c)); return d;
}
__device__ __forceinline__ double fadd2(double a, double b) {
    double d; asm("add.rn.f32x2 %0,%1,%2;" : "=d"(d) : "d"(a), "d"(b)); return d;
}
__device__ __forceinline__ double fmul2(double a, double b) {
    double d; asm("mul.rn.f32x2 %0,%1,%2;" : "=d"(d) : "d"(a), "d"(b)); return d;
}
__device__ __forceinline__ float flo(double d) { return __int_as_float(__double2loint(d)); }
__device__ __forceinline__ float fhi(double d) { return __int_as_float(__double2hiint(d)); }
__device__ __forceinline__ double fpack(float lo, float hi) {
    return __hiloint2double(__float_as_int(hi), __float_as_int(lo));
}

// =====================================================================
// Adjacency bucket build (once per launch): g_bkt[r][i] = col of i-th
// in-edge of node r.  g_deg must be zeroed first (memsetAsync).
// =====================================================================
__global__ void k_build(const int* __restrict__ row, const int* __restrict__ col) {
    int e = blockIdx.x * 256 + threadIdx.x;
    if (e >= N_EDGES) return;
    int r = __ldg(row + e);
    int p = atomicAdd(&g_deg[r], 1);
    if (p < CAP) g_bkt[(size_t)r * CAP + p] = __ldg(col + e);
}

// =====================================================================
// K1: m = relu(h @ Wc^T).  2 threads per node; thread jh computes output
// pairs (4t+2jh, 4t+2jh+1).  W in padded smem (stride WPAD).
// =====================================================================
__global__ void __launch_bounds__(256) k_conv_gemm(
    const float* __restrict__ h, const float* __restrict__ W,
    float* __restrict__ m)
{
    __shared__ __align__(16) float ws[HID * WPAD];
    for (int i = threadIdx.x; i < HID * HID; i += 256) {
        int j = i >> 6, k = i & 63;
        ws[j * WPAD + k] = W[i];
    }
    __syncthreads();

    int nl   = threadIdx.x >> 1;
    int jh   = threadIdx.x & 1;
    int node = blockIdx.x * 128 + nl;
    if (node >= N_NODES) return;

    double hv[32];
    const double2* hrow = reinterpret_cast<const double2*>(h + (size_t)node * HID);
#pragma unroll
    for (int i = 0; i < 16; i++) {
        double2 t = __ldg(hrow + i);
        hv[2 * i] = t.x; hv[2 * i + 1] = t.y;
    }

    float2* mrow = reinterpret_cast<float2*>(m + (size_t)node * HID);
#pragma unroll
    for (int t = 0; t < 16; t++) {
        int j0 = 4 * t + 2 * jh;
        const double2* w0 = reinterpret_cast<const double2*>(ws + j0 * WPAD);
        const double2* w1 = reinterpret_cast<const double2*>(ws + (j0 + 1) * WPAD);
        double a0 = 0.0, b0 = 0.0, a1 = 0.0, b1 = 0.0;
#pragma unroll
        for (int q = 0; q < 16; q++) {
            double2 u = w0[q];
            a0 = ffma2(hv[2 * q],     u.x, a0);
            b0 = ffma2(hv[2 * q + 1], u.y, b0);
            double2 v = w1[q];
            a1 = ffma2(hv[2 * q],     v.x, a1);
            b1 = ffma2(hv[2 * q + 1], v.y, b1);
        }
        double s0 = fadd2(a0, b0), s1 = fadd2(a1, b1);
        float r0 = fmaxf(flo(s0) + fhi(s0), 0.f);
        float r1 = fmaxf(flo(s1) + fhi(s1), 0.f);
        mrow[2 * t + jh] = make_float2(r0, r1);
    }
}

// =====================================================================
// K3: agg = gather-sum of m over in-neighbors (bucket CSR);
//     h' = rmsnorm(h+agg, cnw);  y = relu(h' @ Wh^T);
//     out = rmsnorm(h'+y, hnw).
// 2 threads per node: each owns a 32-col k-half for gather+norm1 (halves
// exchanged via shfl_xor(1)), and interleaved output pairs for the GEMM.
// =====================================================================
__global__ void __launch_bounds__(256) k_norm_hid(
    const float* __restrict__ h, const float* __restrict__ W,
    const float* __restrict__ cnw, const float* __restrict__ hnw,
    float* __restrict__ out, const float* __restrict__ m)
{
    __shared__ __align__(16) float ws[HID * WPAD];
    __shared__ __align__(16) float cn[HID];
    __shared__ __align__(16) float hn[HID];
    for (int i = threadIdx.x; i < HID * HID; i += 256) {
        int j = i >> 6, k = i & 63;
        ws[j * WPAD + k] = W[i];
    }
    if (threadIdx.x < HID) {
        cn[threadIdx.x] = cnw[threadIdx.x];
        hn[threadIdx.x] = hnw[threadIdx.x];
    }
    __syncthreads();

    int nl   = threadIdx.x >> 1;
    int jh   = threadIdx.x & 1;
    int node = blockIdx.x * 128 + nl;
    if (node >= N_NODES) return;
    unsigned msk = __activemask();

    // ---- phase 1: gather own k-half, residual, rmsnorm ----
    int kb = jh * 32;
    double acc[16];
    const double2* hrow = reinterpret_cast<const double2*>(h + (size_t)node * HID + kb);
#pragma unroll
    for (int i = 0; i < 8; i++) {
        double2 t = __ldg(hrow + i);
        acc[2 * i] = t.x; acc[2 * i + 1] = t.y;
    }

    int d = g_deg[node]; if (d > CAP) d = CAP;
    const int* bp = g_bkt + (size_t)node * CAP;
    for (int i = 0; i < d; i++) {
        int c = __ldg(bp + i);
        const double2* mr = reinterpret_cast<const double2*>(m + (size_t)c * HID + kb);
#pragma unroll
        for (int q = 0; q < 8; q++) {
            double2 t = __ldg(mr + q);
            acc[2 * q]     = fadd2(acc[2 * q],     t.x);
            acc[2 * q + 1] = fadd2(acc[2 * q + 1], t.y);
        }
    }

    double sqp = 0.0;
#pragma unroll
    for (int i = 0; i < 16; i++) sqp = ffma2(acc[i], acc[i], sqp);
    float ssq = flo(sqp) + fhi(sqp);
    ssq += __shfl_xor_sync(msk, ssq, 1);
    float inv1 = rsqrtf(ssq * (1.f / HID) + EPS);
    double inv1p = fpack(inv1, inv1);

    const double2* cp = reinterpret_cast<const double2*>(cn + kb);
#pragma unroll
    for (int q = 0; q < 8; q++) {
        double2 c = cp[q];
        acc[2 * q]     = fmul2(fmul2(acc[2 * q],     inv1p), c.x);
        acc[2 * q + 1] = fmul2(fmul2(acc[2 * q + 1], inv1p), c.y);
    }

    // ---- exchange halves: build full h' row in registers ----
    double hv[32];
#pragma unroll
    for (int q = 0; q < 16; q++) {
        double o = __shfl_xor_sync(msk, acc[q], 1);
        hv[q]      = jh ? o : acc[q];
        hv[16 + q] = jh ? acc[q] : o;
    }

    // ---- phase 2: hidden GEMM on interleaved output pairs ----
    float2 zz[16];
    float sq2 = 0.f;
#pragma unroll
    for (int t = 0; t < 16; t++) {
        int j0 = 4 * t + 2 * jh;
        const double2* w0 = reinterpret_cast<const double2*>(ws + j0 * WPAD);
        const double2* w1 = reinterpret_cast<const double2*>(ws + (j0 + 1) * WPAD);
        double a0 = 0.0, b0 = 0.0, a1 = 0.0, b1 = 0.0;
#pragma unroll
        for (int q = 0; q < 16; q++) {
            double2 u = w0[q];
            a0 = ffma2(hv[2 * q],     u.x, a0);
            b0 = ffma2(hv[2 * q + 1], u.y, b0);
            double2 v = w1[q];
            a1 = ffma2(hv[2 * q],     v.x, a1);
            b1 = ffma2(hv[2 * q + 1], v.y, b1);
        }
        double s0 = fadd2(a0, b0), s1 = fadd2(a1, b1);
        double hpair = hv[2 * t + jh];   // (h'[j0], h'[j0+1])
        float z0 = flo(hpair) + fmaxf(flo(s0) + fhi(s0), 0.f);
        float z1 = fhi(hpair) + fmaxf(flo(s1) + fhi(s1), 0.f);
        sq2 = fmaf(z0, z0, sq2);
        sq2 = fmaf(z1, z1, sq2);
        zz[t] = make_float2(z0, z1);
    }
    sq2 += __shfl_xor_sync(msk, sq2, 1);
    float inv2 = rsqrtf(sq2 * (1.f / HID) + EPS);

    float2* orow = reinterpret_cast<float2*>(out + (size_t)node * HID);
#pragma unroll
    for (int t = 0; t < 16; t++) {
        int j0 = 4 * t + 2 * jh;
        orow[2 * t + jh] = make_float2(zz[t].x * inv2 * hn[j0],
                                       zz[t].y * inv2 * hn[j0 + 1]);
    }
}

// =====================================================================
extern "C" void kernel_launch(void* const* d_in, const int* in_sizes, int n_in,
                              void* d_out, int out_size)
{
    const float* x         = (const float*)d_in[0];
    const float* conv_w    = (const float*)d_in[1];
    const float* conv_norm = (const float*)d_in[2];
    const float* hid_w     = (const float*)d_in[3];
    const float* hid_norm  = (const float*)d_in[4];
    const int*   row       = (const int*)d_in[5];
    const int*   col       = (const int*)d_in[6];
    float*       out       = (float*)d_out;

    float *mp = nullptr, *hp = nullptr;
    int   *dp = nullptr;
    cudaGetSymbolAddress((void**)&mp, g_m);
    cudaGetSymbolAddress((void**)&hp, g_h);
    cudaGetSymbolAddress((void**)&dp, g_deg);

    // Adjacency buckets (layer-invariant): build once per launch.
    cudaMemsetAsync(dp, 0, N_NODES * sizeof(int));
    k_build<<<(N_EDGES + 255) / 256, 256>>>(row, col);

    const int NB = (N_NODES + 127) / 128;   // 256 threads, 128 nodes/block

    for (int l = 0; l < N_LAYERS; l++) {
        const float* hsrc = (l == 0) ? x : hp;
        float* hdst = (l == N_LAYERS - 1) ? out : hp;
        k_conv_gemm<<<NB, 256>>>(hsrc, conv_w + l * HID * HID, mp);
        k_norm_hid<<<NB, 256>>>(hsrc, hid_w + l * HID * HID,
                                conv_norm + l * HID, hid_norm + l * HID,
                                hdst, mp);
    }
}

// round 8
// speedup vs baseline: 1.8097x; 1.8097x over previous
#include <cuda_runtime.h>
#include <cstdint>

namespace {
constexpr int N_NODES  = 100000;
constexpr int HID      = 64;
constexpr int N_LAYERS = 4;
constexpr int N_EDGES  = 800000;
constexpr float EPS    = 1e-5f;
constexpr int CAP      = 64;   // bucket capacity (Poisson(8); max deg ~< 40)
constexpr int SA_STR   = 68;   // padded smem row stride in floats

// dynamic smem layout (float indices)
constexpr int OF_A   = 0;                    // 128 x 68 fp32 (A rows)
constexpr int OF_WHI = 128 * SA_STR;         // 64 x 68 tf32 bits
constexpr int OF_WLO = OF_WHI + 64 * SA_STR; // 64 x 68 tf32 bits
constexpr int OF_CN  = OF_WLO + 64 * SA_STR; // 64 floats
constexpr int OF_HN  = OF_CN + 64;           // 64 floats
constexpr int SMEM_FLOATS = OF_HN + 64;
constexpr int SMEM_BYTES  = SMEM_FLOATS * 4; // 70144 B
}

// Scratch (no cudaMalloc allowed)
__device__ float g_m  [(size_t)N_NODES * HID];
__device__ float g_agg[(size_t)N_NODES * HID];
__device__ float g_h  [(size_t)N_NODES * HID];
__device__ int   g_deg[N_NODES];
__device__ int   g_bkt[(size_t)N_NODES * CAP];

// ---------------- helpers ----------------
__device__ __forceinline__ uint32_t tf32_of(float a) {
    uint32_t r; asm("cvt.rna.tf32.f32 %0, %1;" : "=r"(r) : "f"(a)); return r;
}
__device__ __forceinline__ void mma_tf32(float* c, const uint32_t* a,
                                         uint32_t b0, uint32_t b1) {
    asm volatile(
        "mma.sync.aligned.m16n8k8.row.col.f32.tf32.tf32.f32 "
        "{%0,%1,%2,%3},{%4,%5,%6,%7},{%8,%9},{%0,%1,%2,%3};"
        : "+f"(c[0]), "+f"(c[1]), "+f"(c[2]), "+f"(c[3])
        : "r"(a[0]), "r"(a[1]), "r"(a[2]), "r"(a[3]), "r"(b0), "r"(b1));
}

// cooperatively split W (64x64 row-major, W[n][k]) into tf32 hi/lo smem tiles
__device__ __forceinline__ void load_W_split(float* sm, const float* __restrict__ W, int tid) {
    uint32_t* whi = (uint32_t*)(sm + OF_WHI);
    uint32_t* wlo = (uint32_t*)(sm + OF_WLO);
    for (int i = tid; i < HID * HID; i += 128) {
        int n = i >> 6, k = i & 63;
        float w = __ldg(W + i);
        uint32_t hb = tf32_of(w);
        whi[n * SA_STR + k] = hb;
        wlo[n * SA_STR + k] = tf32_of(w - __uint_as_float(hb));
    }
}

// MMA mainloop for one m-tile (16 rows starting at rbase). acc[nt][4].
__device__ __forceinline__ void mma_mtile(const float* sm, int rbase, int g, int q,
                                          float acc[8][4]) {
    const float* pA0 = sm + OF_A + (rbase + g) * SA_STR;
    const float* pA1 = pA0 + 8 * SA_STR;
    uint32_t ahi[8][4], alo[8][4];
#pragma unroll
    for (int ks = 0; ks < 8; ks++) {
        float a0 = pA0[8 * ks + q];
        float a1 = pA1[8 * ks + q];
        float a2 = pA0[8 * ks + q + 4];
        float a3 = pA1[8 * ks + q + 4];
        ahi[ks][0] = tf32_of(a0); alo[ks][0] = tf32_of(a0 - __uint_as_float(ahi[ks][0]));
        ahi[ks][1] = tf32_of(a1); alo[ks][1] = tf32_of(a1 - __uint_as_float(ahi[ks][1]));
        ahi[ks][2] = tf32_of(a2); alo[ks][2] = tf32_of(a2 - __uint_as_float(ahi[ks][2]));
        ahi[ks][3] = tf32_of(a3); alo[ks][3] = tf32_of(a3 - __uint_as_float(ahi[ks][3]));
    }
#pragma unroll
    for (int nt = 0; nt < 8; nt++) {
#pragma unroll
        for (int i = 0; i < 4; i++) acc[nt][i] = 0.f;
        const uint32_t* pBh = (const uint32_t*)(sm + OF_WHI) + (8 * nt + g) * SA_STR;
        const uint32_t* pBl = (const uint32_t*)(sm + OF_WLO) + (8 * nt + g) * SA_STR;
#pragma unroll
        for (int ks = 0; ks < 8; ks++) {
            uint32_t bh0 = pBh[8 * ks + q], bh1 = pBh[8 * ks + q + 4];
            uint32_t bl0 = pBl[8 * ks + q], bl1 = pBl[8 * ks + q + 4];
            mma_tf32(acc[nt], ahi[ks], bh0, bh1);
            mma_tf32(acc[nt], ahi[ks], bl0, bl1);
            mma_tf32(acc[nt], alo[ks], bh0, bh1);
        }
    }
}

// =====================================================================
// Bucket build (once per launch). g_deg memset to 0 first.
// =====================================================================
__global__ void k_build(const int* __restrict__ row, const int* __restrict__ col) {
    int e = blockIdx.x * 256 + threadIdx.x;
    if (e >= N_EDGES) return;
    int r = __ldg(row + e);
    int p = atomicAdd(&g_deg[r], 1);
    if (p < CAP) g_bkt[(size_t)r * CAP + p] = __ldg(col + e);
}

// =====================================================================
// K1: m = relu(h @ Wc^T)  via mma.sync tf32 (3xTF32)
// =====================================================================
__global__ void __launch_bounds__(128) k_conv(
    const float* __restrict__ h, const float* __restrict__ W,
    float* __restrict__ m)
{
    extern __shared__ float sm[];
    int tid = threadIdx.x;

    load_W_split(sm, W, tid);

    int node = blockIdx.x * 128 + tid;
    bool valid = node < N_NODES;
    {
        const float4* hr = (const float4*)(h + (size_t)node * HID);
        float4* dst = (float4*)(sm + OF_A + tid * SA_STR);
#pragma unroll
        for (int c = 0; c < 16; c++)
            dst[c] = valid ? __ldg(hr + c) : make_float4(0.f, 0.f, 0.f, 0.f);
    }
    __syncthreads();

    int wid = tid >> 5, lane = tid & 31, g = lane >> 2, q = lane & 3;
#pragma unroll
    for (int mt = 0; mt < 2; mt++) {
        int rbase = 32 * wid + 16 * mt;
        float acc[8][4];
        mma_mtile(sm, rbase, g, q, acc);

        int n0 = blockIdx.x * 128 + rbase + g;
        int n1 = n0 + 8;
        if (n0 < N_NODES) {
            float* mr = m + (size_t)n0 * HID + 2 * q;
#pragma unroll
            for (int nt = 0; nt < 8; nt++)
                *(float2*)(mr + 8 * nt) =
                    make_float2(fmaxf(acc[nt][0], 0.f), fmaxf(acc[nt][1], 0.f));
        }
        if (n1 < N_NODES) {
            float* mr = m + (size_t)n1 * HID + 2 * q;
#pragma unroll
            for (int nt = 0; nt < 8; nt++)
                *(float2*)(mr + 8 * nt) =
                    make_float2(fmaxf(acc[nt][2], 0.f), fmaxf(acc[nt][3], 0.f));
        }
    }
}

// =====================================================================
// K2: agg[r] = sum_{e: row[e]=r} m[col[e]]  — gather, 16 lanes/node
// =====================================================================
__global__ void __launch_bounds__(256) k_agg(
    const float4* __restrict__ m, float4* __restrict__ agg)
{
    int wid  = threadIdx.x >> 5;
    int lane = threadIdx.x & 31;
    int node = (blockIdx.x * 8 + wid) * 2 + (lane >> 4);
    if (node >= N_NODES) return;
    int l = lane & 15;

    int d = g_deg[node]; if (d > CAP) d = CAP;
    const int* bp = g_bkt + (size_t)node * CAP;

    float4 acc = make_float4(0.f, 0.f, 0.f, 0.f);
    int i = 0;
    for (; i + 2 <= d; i += 2) {
        int c0 = __ldg(bp + i);
        int c1 = __ldg(bp + i + 1);
        float4 v0 = __ldg(m + (size_t)c0 * 16 + l);
        float4 v1 = __ldg(m + (size_t)c1 * 16 + l);
        acc.x += v0.x + v1.x; acc.y += v0.y + v1.y;
        acc.z += v0.z + v1.z; acc.w += v0.w + v1.w;
    }
    if (i < d) {
        int c = __ldg(bp + i);
        float4 v = __ldg(m + (size_t)c * 16 + l);
        acc.x += v.x; acc.y += v.y; acc.z += v.z; acc.w += v.w;
    }
    agg[(size_t)node * 16 + l] = acc;
}

// =====================================================================
// K3: h' = rmsnorm(h+agg)*cnw;  y = relu(h' @ Wh^T)  (mma.sync 3xTF32);
//     out = rmsnorm(h'+y)*hnw
// =====================================================================
__global__ void __launch_bounds__(128) k_norm(
    const float* __restrict__ h, const float* __restrict__ agg,
    const float* __restrict__ W, const float* __restrict__ cnw,
    const float* __restrict__ hnw, float* __restrict__ out)
{
    extern __shared__ float sm[];
    int tid = threadIdx.x;

    if (tid < HID) {
        sm[OF_CN + tid] = __ldg(cnw + tid);
        sm[OF_HN + tid] = __ldg(hnw + tid);
    }
    load_W_split(sm, W, tid);
    __syncthreads();

    int node = blockIdx.x * 128 + tid;
    bool valid = node < N_NODES;
    {
        const float4* hr = (const float4*)(h   + (size_t)node * HID);
        const float4* ar = (const float4*)(agg + (size_t)node * HID);
        float v[64];
        float sq = 0.f;
#pragma unroll
        for (int c = 0; c < 16; c++) {
            float4 a = valid ? __ldg(hr + c) : make_float4(0.f, 0.f, 0.f, 0.f);
            float4 b = valid ? __ldg(ar + c) : make_float4(0.f, 0.f, 0.f, 0.f);
            float z0 = a.x + b.x, z1 = a.y + b.y, z2 = a.z + b.z, z3 = a.w + b.w;
            v[4*c] = z0; v[4*c+1] = z1; v[4*c+2] = z2; v[4*c+3] = z3;
            sq = fmaf(z0, z0, sq); sq = fmaf(z1, z1, sq);
            sq = fmaf(z2, z2, sq); sq = fmaf(z3, z3, sq);
        }
        float inv1 = rsqrtf(sq * (1.f / HID) + EPS);
        float* dst = sm + OF_A + tid * SA_STR;
#pragma unroll
        for (int c = 0; c < 16; c++) {
            *(float4*)(dst + 4 * c) = make_float4(
                v[4*c]   * inv1 * sm[OF_CN + 4*c],
                v[4*c+1] * inv1 * sm[OF_CN + 4*c+1],
                v[4*c+2] * inv1 * sm[OF_CN + 4*c+2],
                v[4*c+3] * inv1 * sm[OF_CN + 4*c+3]);
        }
    }
    __syncthreads();

    int wid = tid >> 5, lane = tid & 31, g = lane >> 2, q = lane & 3;
#pragma unroll
    for (int mt = 0; mt < 2; mt++) {
        int rbase = 32 * wid + 16 * mt;
        float acc[8][4];
        mma_mtile(sm, rbase, g, q, acc);

        // two rows per thread: r0 = rbase+g (c0,c1), r1 = r0+8 (c2,c3)
#pragma unroll
        for (int half = 0; half < 2; half++) {
            int r = rbase + g + 8 * half;
            int nd = blockIdx.x * 128 + r;
            const float* hp = sm + OF_A + r * SA_STR + 2 * q;
            float2 z[8];
            float sq2 = 0.f;
#pragma unroll
            for (int nt = 0; nt < 8; nt++) {
                float y0 = fmaxf(acc[nt][2 * half],     0.f);
                float y1 = fmaxf(acc[nt][2 * half + 1], 0.f);
                float2 hv = *(const float2*)(hp + 8 * nt);
                float z0 = hv.x + y0, z1 = hv.y + y1;
                z[nt] = make_float2(z0, z1);
                sq2 = fmaf(z0, z0, sq2);
                sq2 = fmaf(z1, z1, sq2);
            }
            sq2 += __shfl_xor_sync(0xffffffffu, sq2, 1);
            sq2 += __shfl_xor_sync(0xffffffffu, sq2, 2);
            float inv2 = rsqrtf(sq2 * (1.f / HID) + EPS);
            if (nd < N_NODES) {
                float* orow = out + (size_t)nd * HID + 2 * q;
                const float* hn = sm + OF_HN + 2 * q;
#pragma unroll
                for (int nt = 0; nt < 8; nt++) {
                    *(float2*)(orow + 8 * nt) =
                        make_float2(z[nt].x * inv2 * hn[8 * nt],
                                    z[nt].y * inv2 * hn[8 * nt + 1]);
                }
            }
        }
    }
}

// =====================================================================
extern "C" void kernel_launch(void* const* d_in, const int* in_sizes, int n_in,
                              void* d_out, int out_size)
{
    const float* x         = (const float*)d_in[0];
    const float* conv_w    = (const float*)d_in[1];
    const float* conv_norm = (const float*)d_in[2];
    const float* hid_w     = (const float*)d_in[3];
    const float* hid_norm  = (const float*)d_in[4];
    const int*   row       = (const int*)d_in[5];
    const int*   col       = (const int*)d_in[6];
    float*       out       = (float*)d_out;

    float *mp = nullptr, *ap = nullptr, *hp = nullptr;
    int   *dp = nullptr;
    cudaGetSymbolAddress((void**)&mp, g_m);
    cudaGetSymbolAddress((void**)&ap, g_agg);
    cudaGetSymbolAddress((void**)&hp, g_h);
    cudaGetSymbolAddress((void**)&dp, g_deg);

    cudaFuncSetAttribute(k_conv, cudaFuncAttributeMaxDynamicSharedMemorySize, SMEM_BYTES);
    cudaFuncSetAttribute(k_norm, cudaFuncAttributeMaxDynamicSharedMemorySize, SMEM_BYTES);

    // adjacency buckets: layer-invariant, build once per launch
    cudaMemsetAsync(dp, 0, N_NODES * sizeof(int));
    k_build<<<(N_EDGES + 255) / 256, 256>>>(row, col);

    const int NB = (N_NODES + 127) / 128;
    const int AB = (N_NODES + 15) / 16;

    for (int l = 0; l < N_LAYERS; l++) {
        const float* hsrc = (l == 0) ? x : hp;
        float* hdst = (l == N_LAYERS - 1) ? out : hp;
        k_conv<<<NB, 128, SMEM_BYTES>>>(hsrc, conv_w + l * HID * HID, mp);
        k_agg <<<AB, 256>>>((const float4*)mp, (float4*)ap);
        k_norm<<<NB, 128, SMEM_BYTES>>>(hsrc, ap, hid_w + l * HID * HID,
                                        conv_norm + l * HID, hid_norm + l * HID, hdst);
    }
}